// round 2
// baseline (speedup 1.0000x reference)
#include <cuda_runtime.h>
#include <cstdint>

#define N_MAX 65536
#define M_IND 1024
#define KNN 16

// Scratch (static device globals — no allocation allowed)
__device__ unsigned g_idx[N_MAX * KNN];        // selected neighbor indices
__device__ float    g_Su[M_IND * M_IND];       // Su = Lu Lu^T

// ---------------------------------------------------------------------------
// Kernel 1: Su = Lu Lu^T, Lu = tril(raw,-1) + diag(exp(diag(raw)))
// 64x64 tile per 256-thread block, 4x4 register micro-tile, transform on load,
// symmetry: compute only bj<=bi, write both (i,j) and (j,i).
// ---------------------------------------------------------------------------
__global__ void su_kernel(const float* __restrict__ raw) {
    int bj = blockIdx.x, bi = blockIdx.y;
    if (bj > bi) return;
    __shared__ float At[16][68];   // [k][row], padded
    __shared__ float Bt[16][68];
    int tid = threadIdx.x;           // 256 threads
    int tx = tid & 15, ty = tid >> 4;
    int lr = tid >> 2;               // 0..63 row within tile
    int lk = (tid & 3) << 2;         // 0,4,8,12 col group
    int rA = bi << 6, rB = bj << 6;
    int nk = (bj + 1) << 6;          // k <= min(i,j); rest contributes 0

    float acc[4][4];
#pragma unroll
    for (int u = 0; u < 4; u++)
#pragma unroll
        for (int v = 0; v < 4; v++) acc[u][v] = 0.0f;

    for (int kc = 0; kc < nk; kc += 16) {
        int ga = rA + lr;
        float4 va = *(const float4*)(raw + (size_t)ga * M_IND + kc + lk);
        int gb = rB + lr;
        float4 vb = *(const float4*)(raw + (size_t)gb * M_IND + kc + lk);
        float a4[4] = {va.x, va.y, va.z, va.w};
        float b4[4] = {vb.x, vb.y, vb.z, vb.w};
#pragma unroll
        for (int u = 0; u < 4; u++) {
            int gc = kc + lk + u;
            float x = a4[u];
            At[lk + u][lr] = (gc < ga) ? x : ((gc == ga) ? expf(x) : 0.0f);
            float y = b4[u];
            Bt[lk + u][lr] = (gc < gb) ? y : ((gc == gb) ? expf(y) : 0.0f);
        }
        __syncthreads();
#pragma unroll
        for (int kk = 0; kk < 16; kk++) {
            float4 a = *(const float4*)&At[kk][ty << 2];
            float4 b = *(const float4*)&Bt[kk][tx << 2];
            float aa[4] = {a.x, a.y, a.z, a.w};
            float bb[4] = {b.x, b.y, b.z, b.w};
#pragma unroll
            for (int u = 0; u < 4; u++)
#pragma unroll
                for (int v = 0; v < 4; v++)
                    acc[u][v] = fmaf(aa[u], bb[v], acc[u][v]);
        }
        __syncthreads();
    }
#pragma unroll
    for (int u = 0; u < 4; u++)
#pragma unroll
        for (int v = 0; v < 4; v++) {
            int gi = rA + (ty << 2) + u;
            int gj = rB + (tx << 2) + v;
            g_Su[(size_t)gi * M_IND + gj] = acc[u][v];
            g_Su[(size_t)gj * M_IND + gi] = acc[u][v];
        }
}

// ---------------------------------------------------------------------------
// Kernel 2: per-point 16-NN over 1024 inducing points.
// Thread per point; Z in shared as float4(x,y,z,|z|^2).
// EXACT 64-bit keys: (d2_bits << 32) | idx -> fp32 ordering, lower-index ties.
// ---------------------------------------------------------------------------
__global__ void topk_kernel(const float* __restrict__ X,
                            const float* __restrict__ Z, int N) {
    __shared__ float4 zs[M_IND];
    for (int t = threadIdx.x; t < M_IND; t += blockDim.x) {
        float a = Z[3 * t], b = Z[3 * t + 1], c = Z[3 * t + 2];
        zs[t] = make_float4(a, b, c, fmaf(a, a, fmaf(b, b, c * c)));
    }
    __syncthreads();
    int p = blockIdx.x * blockDim.x + threadIdx.x;
    if (p >= N) return;
    float x0 = X[3 * p], x1 = X[3 * p + 1], x2 = X[3 * p + 2];
    float xs = fmaf(x0, x0, fmaf(x1, x1, x2 * x2));
    float n0 = -2.0f * x0, n1 = -2.0f * x1, n2 = -2.0f * x2;

    unsigned long long ks[KNN];
#pragma unroll
    for (int s = 0; s < KNN; s++) {
        float4 z = zs[s];
        float d = fmaxf(fmaf(n0, z.x, fmaf(n1, z.y, fmaf(n2, z.z, xs + z.w))), 0.0f);
        ks[s] = ((unsigned long long)__float_as_uint(d) << 32) | (unsigned)s;
    }
    unsigned long long kmax = ks[0];
#pragma unroll
    for (int s = 1; s < KNN; s++) kmax = max(kmax, ks[s]);

#pragma unroll 4
    for (int i = KNN; i < M_IND; i++) {
        float4 z = zs[i];
        float d = fmaxf(fmaf(n0, z.x, fmaf(n1, z.y, fmaf(n2, z.z, xs + z.w))), 0.0f);
        unsigned long long key =
            ((unsigned long long)__float_as_uint(d) << 32) | (unsigned)i;
        if (key < kmax) {
#pragma unroll
            for (int s = 0; s < KNN; s++) ks[s] = (ks[s] == kmax) ? key : ks[s];
            unsigned long long m = ks[0];
#pragma unroll
            for (int s = 1; s < KNN; s++) m = max(m, ks[s]);
            kmax = m;
        }
    }
    unsigned idx16[KNN];
#pragma unroll
    for (int s = 0; s < KNN; s++) idx16[s] = (unsigned)(ks[s] & 0xFFFFFFFFu);
    uint4* o = (uint4*)(g_idx + (size_t)p * KNN);
    o[0] = make_uint4(idx16[0], idx16[1], idx16[2], idx16[3]);
    o[1] = make_uint4(idx16[4], idx16[5], idx16[6], idx16[7]);
    o[2] = make_uint4(idx16[8], idx16[9], idx16[10], idx16[11]);
    o[3] = make_uint4(idx16[12], idx16[13], idx16[14], idx16[15]);
}

// ---------------------------------------------------------------------------
// Kernel 3: half-warp per point (2 points/warp). A = lKzz + 2e-4 I recomputed
// from Z (no Kzz materialization). fp64 Gauss-Jordan solve A W = lKxz.
// cov = 1 + sum_ij W_i W_j (Su_ij - lKzz_ij) in fp64.
// ---------------------------------------------------------------------------
__global__ void solve_kernel(const float* __restrict__ X,
                             const float* __restrict__ Z,
                             const float* __restrict__ mu,
                             float* __restrict__ out, int N) {
    __shared__ double sA[8][2][16][17];  // [warp][half][row][16 cols + rhs]
    const unsigned FULL = 0xFFFFFFFFu;
    int lane = threadIdx.x & 31;
    int w = threadIdx.x >> 5;
    int half = lane >> 4;
    int l = lane & 15;
    int p = (blockIdx.x << 4) + (w << 1) + half;
    int pc = p < N ? p : N - 1;   // clamp for safety (N=65536 -> exact)

    float x0 = X[3 * pc], x1 = X[3 * pc + 1], x2 = X[3 * pc + 2];
    float xs = fmaf(x0, x0, fmaf(x1, x1, x2 * x2));

    unsigned idxv = g_idx[(size_t)pc * KNN + l];
    float zx = Z[3 * idxv], zy = Z[3 * idxv + 1], zz = Z[3 * idxv + 2];
    float z2 = fmaf(zx, zx, fmaf(zy, zy, zz * zz));
    // rhs = Kxz entry, same algebraic form as reference (sum-of-squares - 2dot)
    float d2r = fmaxf(xs + z2 - 2.0f * fmaf(x0, zx, fmaf(x1, zy, x2 * zz)), 0.0f);
    double rhs = (double)expf(-0.5f * d2r);
    double muv = (double)mu[idxv];

    // Build A (16x16) in fp64; column l, rows i via width-16 shuffles
#pragma unroll
    for (int i = 0; i < 16; i++) {
        float zxi = __shfl_sync(FULL, zx, i, 16);
        float zyi = __shfl_sync(FULL, zy, i, 16);
        float zzi = __shfl_sync(FULL, zz, i, 16);
        float dx = zxi - zx, dy = zyi - zy, dz = zzi - zz;
        float d2 = fmaf(dx, dx, fmaf(dy, dy, dz * dz));
        double a = (i == l) ? (1.0 + 2e-4) : (double)expf(-0.5f * d2);
        sA[w][half][i][l] = a;
    }
    sA[w][half][l][16] = rhs;
    __syncwarp();

    // Gauss-Jordan (SPD, no pivoting): full elimination -> diagonal system
#pragma unroll 1
    for (int k = 0; k < 16; k++) {
        double rp = 1.0 / sA[w][half][k][k];
        if (l != k) {
            double f = sA[w][half][l][k] * rp;
            for (int c = k + 1; c <= 16; c++)
                sA[w][half][l][c] = fma(-f, sA[w][half][k][c], sA[w][half][l][c]);
        }
        __syncwarp();
    }
    double Wv = sA[w][half][l][16] / sA[w][half][l][l];

    // cov = 1 + sum_ij W_i W_j (Su_ij - lKzz_ij); lKzz diag = 1 + 1e-4
    double acc = 0.0;
#pragma unroll
    for (int i = 0; i < 16; i++) {
        double Wi = __shfl_sync(FULL, Wv, i, 16);
        unsigned ia = __shfl_sync(FULL, idxv, i, 16);
        float su = g_Su[(size_t)ia * M_IND + idxv];
        float zxi = __shfl_sync(FULL, zx, i, 16);
        float zyi = __shfl_sync(FULL, zy, i, 16);
        float zzi = __shfl_sync(FULL, zz, i, 16);
        float dx = zxi - zx, dy = zyi - zy, dz = zzi - zz;
        float d2 = fmaf(dx, dx, fmaf(dy, dy, dz * dz));
        float kv = (i == l) ? 1.0001f : expf(-0.5f * d2);
        acc = fma(Wi * Wv, (double)su - (double)kv, acc);
    }
    double mpart = Wv * muv;
#pragma unroll
    for (int o = 8; o > 0; o >>= 1) {
        acc   += __shfl_xor_sync(FULL, acc, o, 16);
        mpart += __shfl_xor_sync(FULL, mpart, o, 16);
    }
    if (l == 0 && p < N) {
        out[p] = (float)mpart;                         // mean
        float cov = (float)(1.0 + acc);
        out[N + p] = sqrtf(fmaxf(cov, 0.05f));         // std
    }
}

// ---------------------------------------------------------------------------
extern "C" void kernel_launch(void* const* d_in, const int* in_sizes, int n_in,
                              void* d_out, int out_size) {
    const float* X      = (const float*)d_in[0];
    const float* Z      = (const float*)d_in[1];
    const float* Lu_raw = (const float*)d_in[2];
    const float* mu     = (const float*)d_in[3];
    float* out = (float*)d_out;
    int N = in_sizes[0] / 3;

    su_kernel<<<dim3(16, 16), 256>>>(Lu_raw);
    topk_kernel<<<(N + 127) / 128, 128>>>(X, Z, N);
    solve_kernel<<<(N + 15) / 16, 256>>>(X, Z, mu, out, N);
}